// round 17
// baseline (speedup 1.0000x reference)
#include <cuda_runtime.h>
#include <cooperative_groups.h>

namespace cg = cooperative_groups;

// FPS, torch_geometric semantics. 16 clouds x 16384 -> 4096 samples/cloud.
// 4-CTA cluster per cloud (64 CTAs), 4096 pts/CTA, min-dists in registers.
// Exchange: owner pushes record to ALL 4 CTAs' slots (plain st.shared::cluster)
// then st.release of flag=iter to all 4; every thread polls its 4 LOCAL flag
// words with plain volatile LDS (broadcast), one ld.acquire per flag for
// ordering, then serial 4-key combine in registers. NO cluster.sync in loop.
// Parity double-buffering + forward dependency (publish(i+2) requires all
// flags of i+1 consumed, which requires all reads of i done) = race-free.
// Bit-exact arithmetic (validated R6+): d=(dx*dx+dy*dy)+dz*dz, RN, no FMA
// contraction, sub = add of negated. Keys: high=dist bits, low=~idx (first-
// occurrence argmax). redux two-step validated R12+.
// Output: float32 values of global indices.

#define N_CLOUDS 16
#define PTS      16384
#define M_SAMP   4096
#define THREADS  512
#define CL       4
#define QTR      4096
#define PAIRS    4       // 8 points per thread = 4 f32x2 pairs
#define NW       16      // warps per CTA

__device__ __forceinline__ unsigned long long pack2(float lo, float hi) {
    unsigned long long r;
    asm("mov.b64 %0, {%1, %2};" : "=l"(r) : "f"(lo), "f"(hi));
    return r;
}
__device__ __forceinline__ void unpack2(unsigned long long v, float& lo, float& hi) {
    asm("mov.b64 {%0, %1}, %2;" : "=f"(lo), "=f"(hi) : "l"(v));
}
// Packed IEEE RN f32x2 ops (sm_100+): bit-identical to scalar FADD/FMUL.
__device__ __forceinline__ unsigned long long add2(unsigned long long a, unsigned long long b) {
    unsigned long long r;
    asm("add.rn.f32x2 %0, %1, %2;" : "=l"(r) : "l"(a), "l"(b));
    return r;
}
__device__ __forceinline__ unsigned long long mul2(unsigned long long a, unsigned long long b) {
    unsigned long long r;
    asm("mul.rn.f32x2 %0, %1, %2;" : "=l"(r) : "l"(a), "l"(b));
    return r;
}
__device__ __forceinline__ unsigned int redux_umax(unsigned int v) {
    unsigned int r;
    asm("redux.sync.max.u32 %0, %1, 0xffffffff;" : "=r"(r) : "r"(v));
    return r;
}
__device__ __forceinline__ unsigned int smem_u32(const void* p) {
    unsigned int a;
    asm("{ .reg .u64 t; cvta.to.shared.u64 t, %1; cvt.u32.u64 %0, t; }" : "=r"(a) : "l"(p));
    return a;
}
__device__ __forceinline__ unsigned int mapa_u32(unsigned int local_addr, unsigned int peer) {
    unsigned int r;
    asm("mapa.shared::cluster.u32 %0, %1, %2;" : "=r"(r) : "r"(local_addr), "r"(peer));
    return r;
}

// Record: [0]=key u64, [8]=xy u64, [16]=z f32, pad to 24.
#define SLOT_B 24

__global__ __launch_bounds__(THREADS, 1) __cluster_dims__(CL, 1, 1)
void fps_kernel(const float* __restrict__ pos, float* __restrict__ out)
{
    __shared__ unsigned long long skeys[2][NW];                    // [par][warp]
    __shared__ __align__(8) unsigned char slots[2][CL * SLOT_B];   // [par][rank]
    __shared__ unsigned int flags[2][CL];                          // [par][rank]

    cg::cluster_group cluster = cg::this_cluster();
    const unsigned rank = cluster.block_rank();          // 0..3
    const int b    = blockIdx.x >> 2;                    // cloud id
    const int base = (int)rank * QTR;

    const int t    = threadIdx.x;
    const int lane = t & 31;
    const int wid  = t >> 5;
    const float* p = pos + (size_t)b * PTS * 3;

    const unsigned int slots_a = smem_u32(&slots[0][0]);
    const unsigned int flags_a = smem_u32(&flags[0][0]);

    if (t == 0) {
#pragma unroll
        for (int pa = 0; pa < 2; ++pa)
#pragma unroll
            for (int r = 0; r < CL; ++r) flags[pa][r] = 0u;
    }

    // This thread's 8 points: cloud-local index g = base + t + (k<<9), k=0..7.
    unsigned long long CX[PAIRS], CY[PAIRS], CZ[PAIRS];
    float d[2 * PAIRS];
    const float INF = __int_as_float(0x7f800000);

#pragma unroll
    for (int pr = 0; pr < PAIRS; ++pr) {
        int g0 = base + t + ((2 * pr)     << 9);
        int g1 = base + t + ((2 * pr + 1) << 9);
        CX[pr] = pack2(p[3 * g0 + 0], p[3 * g1 + 0]);
        CY[pr] = pack2(p[3 * g0 + 1], p[3 * g1 + 1]);
        CZ[pr] = pack2(p[3 * g0 + 2], p[3 * g1 + 2]);
        d[2 * pr]     = INF;
        d[2 * pr + 1] = INF;
    }

    // First pick: cloud-local index 0 (L1-broadcast global load).
    float sx = p[0], sy = p[1], sz = p[2];
    if (t == 0 && rank == 0) out[b * M_SAMP] = (float)(b * PTS);

    // Flag init visible cluster-wide before any publish.
    cluster.sync();

    for (int i = 1; i < M_SAMP; ++i) {
        const unsigned long long nx2 = pack2(-sx, -sx);
        const unsigned long long ny2 = pack2(-sy, -sy);
        const unsigned long long nz2 = pack2(-sz, -sz);

        float best = 0.0f;
        int jj = 0;

#pragma unroll
        for (int pr = 0; pr < PAIRS; ++pr) {
            unsigned long long dx = add2(CX[pr], nx2);       // exact sub
            unsigned long long dy = add2(CY[pr], ny2);
            unsigned long long dz = add2(CZ[pr], nz2);
            unsigned long long s  = add2(add2(mul2(dx, dx), mul2(dy, dy)), mul2(dz, dz));
            float lo, hi;
            unpack2(s, lo, hi);
            {
                float nd = fminf(d[2 * pr], lo);
                d[2 * pr] = nd;
                bool c = nd > best; best = c ? nd : best; jj = c ? 2 * pr : jj;
            }
            {
                float nd = fminf(d[2 * pr + 1], hi);
                d[2 * pr + 1] = nd;
                bool c = nd > best; best = c ? nd : best; jj = c ? 2 * pr + 1 : jj;
            }
        }

        // Key: high = dist bits (>=0, order-preserving), low = ~cloud_local_idx.
        const unsigned int gidx   = (unsigned int)(base + t) + ((unsigned int)jj << 9);
        const unsigned int mybits = __float_as_uint(best);
        const unsigned int myinv  = 0xFFFFFFFFu - gidx;

        // Warp argmax via 2 hardware reductions (bit-identical to u64 max).
        const unsigned int wbits = redux_umax(mybits);
        const unsigned int winv  = redux_umax(mybits == wbits ? myinv : 0u);

        const int par = i & 1;
        if (lane == 0)
            skeys[par][wid] = ((unsigned long long)wbits << 32) | winv;
        __syncthreads();

        // CTA scan of 16 warp keys via redux.
        unsigned long long kw = (lane < NW) ? skeys[par][lane] : 0ull;
        const unsigned int chb = (unsigned int)(kw >> 32);
        const unsigned int crb = redux_umax(chb);
        const unsigned int cri = redux_umax(chb == crb ? (unsigned int)kw : 0u);

        // UNIQUE owner publishes record + release-flag to ALL 4 CTAs.
        if (mybits == crb && myinv == cri) {
            const int prw = jj >> 1;
            const int hw  = jj & 1;
            float wx = 0.f, wy = 0.f, wz = 0.f;
#pragma unroll
            for (int pr = 0; pr < PAIRS; ++pr) {
                if (pr == prw) {
                    float l0, h0, l1, h1, l2, h2;
                    unpack2(CX[pr], l0, h0);
                    unpack2(CY[pr], l1, h1);
                    unpack2(CZ[pr], l2, h2);
                    wx = hw ? h0 : l0;
                    wy = hw ? h1 : l1;
                    wz = hw ? h2 : l2;
                }
            }
            const unsigned long long key64 =
                ((unsigned long long)crb << 32) | (unsigned long long)cri;
            const unsigned long long xy = pack2(wx, wy);
            const unsigned int myslot = slots_a
                + (unsigned)par * (CL * SLOT_B) + rank * SLOT_B;
            const unsigned int myflag = flags_a
                + (unsigned)par * (CL * 4) + rank * 4;
            // Record stores to all ranks (plain), then release flag stores.
#pragma unroll
            for (unsigned r = 0; r < CL; ++r) {
                const unsigned int rs = mapa_u32(myslot, r);
                asm volatile("st.shared::cluster.b64 [%0],    %1;" :: "r"(rs), "l"(key64) : "memory");
                asm volatile("st.shared::cluster.b64 [%0+8],  %1;" :: "r"(rs), "l"(xy)    : "memory");
                asm volatile("st.shared::cluster.f32 [%0+16], %1;" :: "r"(rs), "f"(wz)    : "memory");
            }
#pragma unroll
            for (unsigned r = 0; r < CL; ++r) {
                const unsigned int rf = mapa_u32(myflag, r);
                asm volatile("st.release.cluster.shared::cluster.b32 [%0], %1;"
                             :: "r"(rf), "r"((unsigned)i) : "memory");
            }
        }

        // Poll the 4 LOCAL flag words (cheap broadcast LDS), then one acquire
        // load per flag to order the record reads after the peer's stores.
        {
            const unsigned int fb = flags_a + (unsigned)par * (CL * 4);
#pragma unroll
            for (int r = 0; r < CL; ++r) {
                const unsigned int fa = fb + (unsigned)r * 4;
                unsigned int v;
                do {
                    asm volatile("ld.volatile.shared.u32 %0, [%1];" : "=r"(v) : "r"(fa));
                } while (v != (unsigned)i);
                asm volatile("ld.acquire.cluster.shared::cta.b32 %0, [%1];"
                             : "=r"(v) : "r"(fa) : "memory");
            }
        }

        // Serial combine of 4 records in registers (keys globally unique).
        const unsigned int sb = slots_a + (unsigned)par * (CL * SLOT_B);
        unsigned long long k0, k1, k2, k3;
        asm volatile("ld.shared.b64 %0, [%1];"    : "=l"(k0) : "r"(sb)              : "memory");
        asm volatile("ld.shared.b64 %0, [%1+24];" : "=l"(k1) : "r"(sb)              : "memory");
        asm volatile("ld.shared.b64 %0, [%1+48];" : "=l"(k2) : "r"(sb)              : "memory");
        asm volatile("ld.shared.b64 %0, [%1+72];" : "=l"(k3) : "r"(sb)              : "memory");
        unsigned long long gk = k0; unsigned int ws = 0;
        if (k1 > gk) { gk = k1; ws = 1; }
        if (k2 > gk) { gk = k2; ws = 2; }
        if (k3 > gk) { gk = k3; ws = 3; }
        const unsigned int wa = sb + ws * SLOT_B;
        unsigned long long wxy; float wz;
        asm volatile("ld.shared.b64 %0, [%1+8];"  : "=l"(wxy) : "r"(wa) : "memory");
        asm volatile("ld.shared.f32 %0, [%1+16];" : "=f"(wz)  : "r"(wa) : "memory");
        unpack2(wxy, sx, sy);
        sz = wz;

        if (t == 0 && rank == 0) {
            const unsigned int gw = 0xFFFFFFFFu - (unsigned int)gk;
            out[b * M_SAMP + i] = (float)(b * PTS + (int)gw);
        }
    }

    // Belt-and-braces: no CTA exits while peers could still be writing here.
    cluster.sync();
}

extern "C" void kernel_launch(void* const* d_in, const int* in_sizes, int n_in,
                              void* d_out, int out_size)
{
    // Resolve pos BY SIZE (786432 floats), robust to input ordering.
    const float* pos = nullptr;
    for (int i = 0; i < n_in; ++i) {
        if (in_sizes[i] == N_CLOUDS * PTS * 3) { pos = (const float*)d_in[i]; break; }
    }
    if (!pos) pos = (const float*)d_in[0];

    float* out = (float*)d_out;   // [N_CLOUDS*M_SAMP] float32 index values

    fps_kernel<<<N_CLOUDS * CL, THREADS>>>(pos, out);
}